// round 1
// baseline (speedup 1.0000x reference)
#include <cuda_runtime.h>
#include <math.h>
#include <stdint.h>

#define B_  4
#define T_  1024
#define E_  1024
#define H_  16
#define HD  64
#define L_  6
#define FF_ 4096
#define V_  32000
#define BT  (B_ * T_)

// ---------------- device scratch (static, no allocations) ----------------
__device__ float g_x[BT * E_];
__device__ float g_q[BT * E_];
__device__ float g_k[BT * E_];
__device__ float g_v[BT * E_];
__device__ float g_attn[BT * E_];
__device__ float g_tmp[BT * E_];
__device__ float g_ff[(size_t)BT * FF_];
__device__ float g_scores[(size_t)B_ * H_ * T_ * T_];   // 256 MiB

// ---------------- warp/block reductions ----------------
__device__ __forceinline__ float warpSum(float v) {
    #pragma unroll
    for (int o = 16; o > 0; o >>= 1) v += __shfl_xor_sync(0xffffffffu, v, o);
    return v;
}
__device__ __forceinline__ float warpMax(float v) {
    #pragma unroll
    for (int o = 16; o > 0; o >>= 1) v = fmaxf(v, __shfl_xor_sync(0xffffffffu, v, o));
    return v;
}

// ---------------- embedding: x[b,t,:] = tok[idx[b,t],:] + pos[t,:] ----------------
__global__ void embed_kernel(const int* __restrict__ idx,
                             const float* __restrict__ tok,
                             const float* __restrict__ pos,
                             float* __restrict__ x) {
    int bt = blockIdx.x;
    int t  = bt & (T_ - 1);
    int id = idx[bt];
    int c  = threadIdx.x;                 // 256 threads, float4 each = 1024 floats
    float4 a = ((const float4*)(tok + (size_t)id * E_))[c];
    float4 p = ((const float4*)(pos + (size_t)t  * E_))[c];
    a.x += p.x; a.y += p.y; a.z += p.z; a.w += p.w;
    ((float4*)(x + (size_t)bt * E_))[c] = a;
}

// ---------------- SGEMM: C = A(MxK) * B(KxN) + bias, optional ReLU ----------------
// Requires: M%128==0, N%128==0, K%16==0 (true for all shapes used here).
template<bool RELU>
__global__ __launch_bounds__(256, 2)
void sgemm_kernel(const float* __restrict__ A, const float* __restrict__ B,
                  const float* __restrict__ bias, float* __restrict__ C,
                  int M, int N, int K) {
    __shared__ float As[16][128];   // transposed: As[k][m]
    __shared__ float Bs[16][128];   // Bs[k][n]
    int tid = threadIdx.x;
    int tx = tid & 15, ty = tid >> 4;
    int bm = blockIdx.y * 128, bn = blockIdx.x * 128;

    const float* Ab = A + (size_t)bm * K;
    const float* Bb = B + bn;

    int arow = tid >> 2;            // 0..63
    int acol = (tid & 3) * 4;       // 0,4,8,12
    int brow = tid >> 5;            // 0..7
    int bcol = (tid & 31) * 4;      // 0..124

    float acc[8][8];
    #pragma unroll
    for (int i = 0; i < 8; i++)
        #pragma unroll
        for (int j = 0; j < 8; j++) acc[i][j] = 0.f;

    for (int k0 = 0; k0 < K; k0 += 16) {
        #pragma unroll
        for (int rr = 0; rr < 2; rr++) {
            float4 a = *(const float4*)(Ab + (size_t)(arow + rr * 64) * K + k0 + acol);
            As[acol + 0][arow + rr * 64] = a.x;
            As[acol + 1][arow + rr * 64] = a.y;
            As[acol + 2][arow + rr * 64] = a.z;
            As[acol + 3][arow + rr * 64] = a.w;
        }
        #pragma unroll
        for (int rr = 0; rr < 2; rr++) {
            float4 b4 = *(const float4*)(Bb + (size_t)(k0 + brow + rr * 8) * N + bcol);
            *(float4*)&Bs[brow + rr * 8][bcol] = b4;
        }
        __syncthreads();

        #pragma unroll
        for (int k = 0; k < 16; k++) {
            float ra[8], rb[8];
            *(float4*)&ra[0] = *(const float4*)&As[k][ty * 8];
            *(float4*)&ra[4] = *(const float4*)&As[k][ty * 8 + 4];
            *(float4*)&rb[0] = *(const float4*)&Bs[k][tx * 8];
            *(float4*)&rb[4] = *(const float4*)&Bs[k][tx * 8 + 4];
            #pragma unroll
            for (int i = 0; i < 8; i++)
                #pragma unroll
                for (int j = 0; j < 8; j++)
                    acc[i][j] = fmaf(ra[i], rb[j], acc[i][j]);
        }
        __syncthreads();
    }

    #pragma unroll
    for (int i = 0; i < 8; i++) {
        int row = bm + ty * 8 + i;
        #pragma unroll
        for (int j = 0; j < 8; j += 4) {
            int col = bn + tx * 8 + j;
            float4 v;
            v.x = acc[i][j]; v.y = acc[i][j + 1]; v.z = acc[i][j + 2]; v.w = acc[i][j + 3];
            v.x += bias[col]; v.y += bias[col + 1]; v.z += bias[col + 2]; v.w += bias[col + 3];
            if (RELU) {
                v.x = fmaxf(v.x, 0.f); v.y = fmaxf(v.y, 0.f);
                v.z = fmaxf(v.z, 0.f); v.w = fmaxf(v.w, 0.f);
            }
            *(float4*)(C + (size_t)row * N + col) = v;
        }
    }
}

// ---------------- attention scores: S[bh,i,j] = dot(Q,K)/8, causal ----------------
// grid (jt=16, it=16, bh=64), block 256. Only jt<=it tiles computed.
__global__ void attn_scores_kernel(const float* __restrict__ Q,
                                   const float* __restrict__ Kb,
                                   float* __restrict__ S) {
    int jt = blockIdx.x, it = blockIdx.y, bh = blockIdx.z;
    if (jt > it) return;
    int b = bh >> 4, h = bh & 15;

    __shared__ float Qs[64][65];
    __shared__ float Ks[64][65];
    int tid = threadIdx.x;
    #pragma unroll
    for (int p = 0; p < 4; p++) {
        int r = p * 16 + (tid >> 4);
        int c = (tid & 15) * 4;
        float4 qv = *(const float4*)(Q + ((size_t)(b * T_ + it * 64 + r) * E_) + h * HD + c);
        Qs[r][c] = qv.x; Qs[r][c + 1] = qv.y; Qs[r][c + 2] = qv.z; Qs[r][c + 3] = qv.w;
        float4 kv = *(const float4*)(Kb + ((size_t)(b * T_ + jt * 64 + r) * E_) + h * HD + c);
        Ks[r][c] = kv.x; Ks[r][c + 1] = kv.y; Ks[r][c + 2] = kv.z; Ks[r][c + 3] = kv.w;
    }
    __syncthreads();

    int tx = tid & 15, ty = tid >> 4;
    float acc[4][4] = {};
    #pragma unroll 8
    for (int d = 0; d < 64; d++) {
        float rq[4], rk[4];
        #pragma unroll
        for (int ii = 0; ii < 4; ii++) rq[ii] = Qs[ty * 4 + ii][d];
        #pragma unroll
        for (int jj = 0; jj < 4; jj++) rk[jj] = Ks[tx * 4 + jj][d];
        #pragma unroll
        for (int ii = 0; ii < 4; ii++)
            #pragma unroll
            for (int jj = 0; jj < 4; jj++)
                acc[ii][jj] = fmaf(rq[ii], rk[jj], acc[ii][jj]);
    }

    #pragma unroll
    for (int ii = 0; ii < 4; ii++) {
        int ig = it * 64 + ty * 4 + ii;
        #pragma unroll
        for (int jj = 0; jj < 4; jj++) {
            int jg = jt * 64 + tx * 4 + jj;
            float v = acc[ii][jj] * 0.125f;          // 1/sqrt(64)
            if (jg > ig) v = -1e30f;
            S[((size_t)bh * T_ + ig) * T_ + jg] = v;
        }
    }
}

// ---------------- row softmax over j <= i (in place) ----------------
__global__ void softmax_kernel(float* __restrict__ S) {
    int rid = blockIdx.x;
    int bh = rid >> 10, i = rid & 1023;
    float* row = S + ((size_t)bh * T_ + i) * T_;
    int n = i + 1;
    int t = threadIdx.x;                   // 128 threads

    float vals[8];
    float m = -1e30f;
    #pragma unroll
    for (int k = 0; k < 8; k++) {
        int j = t + k * 128;
        vals[k] = (j < n) ? row[j] : -1e30f;
        m = fmaxf(m, vals[k]);
    }
    __shared__ float sh[8];
    m = warpMax(m);
    int w = t >> 5, lane = t & 31;
    if (lane == 0) sh[w] = m;
    __syncthreads();
    if (w == 0) {
        float a = (lane < 4) ? sh[lane] : -1e30f;
        a = warpMax(a);
        if (lane == 0) sh[0] = a;
    }
    __syncthreads();
    float M = sh[0];

    float s = 0.f;
    #pragma unroll
    for (int k = 0; k < 8; k++) {
        int j = t + k * 128;
        if (j < n) { vals[k] = expf(vals[k] - M); s += vals[k]; }
    }
    __syncthreads();
    s = warpSum(s);
    if (lane == 0) sh[w] = s;
    __syncthreads();
    if (w == 0) {
        float a = (lane < 4) ? sh[lane] : 0.f;
        a = warpSum(a);
        if (lane == 0) sh[0] = a;
    }
    __syncthreads();
    float inv = 1.f / sh[0];

    #pragma unroll
    for (int k = 0; k < 8; k++) {
        int j = t + k * 128;
        if (j < n) row[j] = vals[k] * inv;
    }
}

// ---------------- O[b,i,h,:] = sum_j P[bh,i,j] V[b,j,h,:] ----------------
// grid (it=16, bh=64), block 256; loops jt = 0..it (triangular).
__global__ void attn_av_kernel(const float* __restrict__ S,
                               const float* __restrict__ Vb,
                               float* __restrict__ O) {
    int it = blockIdx.x, bh = blockIdx.y;
    int b = bh >> 4, h = bh & 15;
    __shared__ float Ps[64][65];
    __shared__ float Vs[64][65];
    int tid = threadIdx.x;
    int tx = tid & 15, ty = tid >> 4;
    float acc[4][4] = {};

    for (int jt = 0; jt <= it; jt++) {
        #pragma unroll
        for (int p = 0; p < 4; p++) {
            int r = p * 16 + (tid >> 4);
            int c = (tid & 15) * 4;
            int ig = it * 64 + r;
            int jg = jt * 64 + c;
            float4 s4 = *(const float4*)(S + ((size_t)bh * T_ + ig) * T_ + jg);
            Ps[r][c + 0] = (jg + 0 <= ig) ? s4.x : 0.f;
            Ps[r][c + 1] = (jg + 1 <= ig) ? s4.y : 0.f;
            Ps[r][c + 2] = (jg + 2 <= ig) ? s4.z : 0.f;
            Ps[r][c + 3] = (jg + 3 <= ig) ? s4.w : 0.f;
            float4 vv = *(const float4*)(Vb + ((size_t)(b * T_ + jt * 64 + r) * E_) + h * HD + c);
            Vs[r][c] = vv.x; Vs[r][c + 1] = vv.y; Vs[r][c + 2] = vv.z; Vs[r][c + 3] = vv.w;
        }
        __syncthreads();
        #pragma unroll 8
        for (int j = 0; j < 64; j++) {
            float rp[4], rv[4];
            #pragma unroll
            for (int ii = 0; ii < 4; ii++) rp[ii] = Ps[ty * 4 + ii][j];
            #pragma unroll
            for (int jj = 0; jj < 4; jj++) rv[jj] = Vs[j][tx * 4 + jj];
            #pragma unroll
            for (int ii = 0; ii < 4; ii++)
                #pragma unroll
                for (int jj = 0; jj < 4; jj++)
                    acc[ii][jj] = fmaf(rp[ii], rv[jj], acc[ii][jj]);
        }
        __syncthreads();
    }

    #pragma unroll
    for (int ii = 0; ii < 4; ii++) {
        int ig = it * 64 + ty * 4 + ii;
        #pragma unroll
        for (int jj = 0; jj < 4; jj++)
            O[((size_t)(b * T_ + ig)) * E_ + h * HD + tx * 4 + jj] = acc[ii][jj];
    }
}

// ---------------- out = LayerNorm(in (+ res)) * g + b ----------------
__global__ void add_ln_kernel(const float* __restrict__ in,
                              const float* __restrict__ res,    // nullable
                              const float* __restrict__ g,
                              const float* __restrict__ bb,
                              float* __restrict__ out) {
    int row = blockIdx.x;
    int t = threadIdx.x;                        // 256 threads * float4 = 1024
    float4 v = ((const float4*)(in + (size_t)row * E_))[t];
    if (res) {
        float4 r = ((const float4*)(res + (size_t)row * E_))[t];
        v.x += r.x; v.y += r.y; v.z += r.z; v.w += r.w;
    }
    float s  = v.x + v.y + v.z + v.w;
    float s2 = v.x * v.x + v.y * v.y + v.z * v.z + v.w * v.w;

    __shared__ float sh[16];
    s = warpSum(s); s2 = warpSum(s2);
    int w = t >> 5, lane = t & 31;
    if (lane == 0) { sh[w] = s; sh[w + 8] = s2; }
    __syncthreads();
    if (w == 0) {
        float a  = (lane < 8) ? sh[lane] : 0.f;
        a = warpSum(a);
        float a2 = (lane < 8) ? sh[lane + 8] : 0.f;
        a2 = warpSum(a2);
        if (lane == 0) { sh[0] = a; sh[8] = a2; }
    }
    __syncthreads();
    float mean = sh[0] * (1.f / E_);
    float var  = sh[8] * (1.f / E_) - mean * mean;
    float rstd = rsqrtf(var + 1e-5f);

    float4 gv = ((const float4*)g)[t];
    float4 bv = ((const float4*)bb)[t];
    float4 o;
    o.x = (v.x - mean) * rstd * gv.x + bv.x;
    o.y = (v.y - mean) * rstd * gv.y + bv.y;
    o.z = (v.z - mean) * rstd * gv.z + bv.z;
    o.w = (v.w - mean) * rstd * gv.w + bv.w;
    ((float4*)(out + (size_t)row * E_))[t] = o;
}

// ---------------- host launch ----------------
extern "C" void kernel_launch(void* const* d_in, const int* in_sizes, int n_in,
                              void* d_out, int out_size) {
    const int*   idx   = (const int*)  d_in[0];
    const float* tok   = (const float*)d_in[1];
    const float* pos   = (const float*)d_in[2];
    const float* Wq    = (const float*)d_in[3];
    const float* bq    = (const float*)d_in[4];
    const float* Wk    = (const float*)d_in[5];
    const float* bk    = (const float*)d_in[6];
    const float* Wv    = (const float*)d_in[7];
    const float* bv    = (const float*)d_in[8];
    const float* Wo    = (const float*)d_in[9];
    const float* bo    = (const float*)d_in[10];
    const float* W1    = (const float*)d_in[11];
    const float* b1    = (const float*)d_in[12];
    const float* W2    = (const float*)d_in[13];
    const float* b2    = (const float*)d_in[14];
    const float* ln1g  = (const float*)d_in[15];
    const float* ln1b  = (const float*)d_in[16];
    const float* ln2g  = (const float*)d_in[17];
    const float* ln2b  = (const float*)d_in[18];
    const float* lnfg  = (const float*)d_in[19];
    const float* lnfb  = (const float*)d_in[20];
    const float* Whead = (const float*)d_in[21];
    const float* bhead = (const float*)d_in[22];
    float* out = (float*)d_out;

    float *x, *q, *k, *v, *attn, *tmp, *ff, *scores;
    cudaGetSymbolAddress((void**)&x,      g_x);
    cudaGetSymbolAddress((void**)&q,      g_q);
    cudaGetSymbolAddress((void**)&k,      g_k);
    cudaGetSymbolAddress((void**)&v,      g_v);
    cudaGetSymbolAddress((void**)&attn,   g_attn);
    cudaGetSymbolAddress((void**)&tmp,    g_tmp);
    cudaGetSymbolAddress((void**)&ff,     g_ff);
    cudaGetSymbolAddress((void**)&scores, g_scores);

    embed_kernel<<<BT, 256>>>(idx, tok, pos, x);

    dim3 gEE(E_ / 128, BT / 128);      // N=1024
    dim3 gEF(FF_ / 128, BT / 128);     // N=4096
    dim3 gHead(V_ / 128, BT / 128);    // N=32000

    for (int l = 0; l < L_; l++) {
        const float* Wq_l = Wq + (size_t)l * E_ * E_;
        const float* Wk_l = Wk + (size_t)l * E_ * E_;
        const float* Wv_l = Wv + (size_t)l * E_ * E_;
        const float* Wo_l = Wo + (size_t)l * E_ * E_;
        const float* W1_l = W1 + (size_t)l * E_ * FF_;
        const float* W2_l = W2 + (size_t)l * FF_ * E_;
        const float* bq_l = bq + l * E_;
        const float* bk_l = bk + l * E_;
        const float* bv_l = bv + l * E_;
        const float* bo_l = bo + l * E_;
        const float* b1_l = b1 + l * FF_;
        const float* b2_l = b2 + l * E_;

        sgemm_kernel<false><<<gEE, 256>>>(x, Wq_l, bq_l, q, BT, E_, E_);
        sgemm_kernel<false><<<gEE, 256>>>(x, Wk_l, bk_l, k, BT, E_, E_);
        sgemm_kernel<false><<<gEE, 256>>>(x, Wv_l, bv_l, v, BT, E_, E_);

        attn_scores_kernel<<<dim3(16, 16, B_ * H_), 256>>>(q, k, scores);
        softmax_kernel<<<B_ * H_ * T_, 128>>>(scores);
        attn_av_kernel<<<dim3(16, B_ * H_), 256>>>(scores, v, attn);

        sgemm_kernel<false><<<gEE, 256>>>(attn, Wo_l, bo_l, tmp, BT, E_, E_);
        add_ln_kernel<<<BT, 256>>>(x, tmp, ln1g + l * E_, ln1b + l * E_, x);

        sgemm_kernel<true ><<<gEF, 256>>>(x, W1_l, b1_l, ff, BT, FF_, E_);
        sgemm_kernel<false><<<gEE, 256>>>(ff, W2_l, b2_l, tmp, BT, E_, FF_);
        add_ln_kernel<<<BT, 256>>>(x, tmp, ln2g + l * E_, ln2b + l * E_, x);
    }

    add_ln_kernel<<<BT, 256>>>(x, nullptr, lnfg, lnfb, x);
    sgemm_kernel<false><<<gHead, 256>>>(x, Whead, bhead, out, BT, V_, E_);
}